// round 9
// baseline (speedup 1.0000x reference)
#include <cuda_runtime.h>
#include <cuda_bf16.h>
#include <cuda_fp16.h>
#include <cstdint>
#include <math.h>

#define Bdim 2
#define Tdim 2048
#define Cdim 768
#define Hdim 12
#define Ddim 64
#define Ldim 6
#define Vdim 50257
#define Mdim (Bdim*Tdim)      /* 4096 */
#define C3   (3*Cdim)         /* 2304 */
#define Fdim (4*Cdim)         /* 3072 */

// ===================== device scratch (no allocations) ======================
__device__ float g_h  [Mdim*Cdim];
__device__ float g_rowloss[Mdim];

__device__ __half g_wqkv_h[Ldim*C3*Cdim];
__device__ __half g_wff1_h[Ldim*Fdim*Cdim];
__device__ __half g_wff2_h[Ldim*Cdim*Fdim];
__device__ __half g_wlm_h[(size_t)Vdim*Cdim];
__device__ __half g_xn_hi[Mdim*Cdim],  g_xn_lo[Mdim*Cdim];
__device__ __half g_ffh_hi[Mdim*Fdim], g_ffh_lo[Mdim*Fdim];
__device__ __half g_ah_h[Mdim*Cdim];
__device__ __half g_qkv_hi[Mdim*C3],   g_qkv_lo[Mdim*C3];

// ===================== asm helpers (baseline sm_80+ ISA) ====================
__device__ __forceinline__ uint32_t smem_to_u32(const void* p) {
    uint32_t a;
    asm("{ .reg .u64 t; cvta.to.shared.u64 t, %1; cvt.u32.u64 %0, t; }" : "=r"(a) : "l"(p));
    return a;
}
__device__ __forceinline__ void cp_async16(uint32_t dst, const void* src){
    asm volatile("cp.async.cg.shared.global [%0], [%1], 16;" :: "r"(dst), "l"(src));
}
#define CP_COMMIT() asm volatile("cp.async.commit_group;" ::: "memory")
#define CP_WAIT0()  asm volatile("cp.async.wait_group 0;" ::: "memory")

__device__ __forceinline__ void ldsm_x4(uint32_t* r, uint32_t addr){
    asm volatile("ldmatrix.sync.aligned.m8n8.x4.shared.b16 {%0,%1,%2,%3}, [%4];"
        : "=r"(r[0]), "=r"(r[1]), "=r"(r[2]), "=r"(r[3]) : "r"(addr));
}
__device__ __forceinline__ void ldsm_x4_t(uint32_t* r, uint32_t addr){
    asm volatile("ldmatrix.sync.aligned.m8n8.x4.trans.shared.b16 {%0,%1,%2,%3}, [%4];"
        : "=r"(r[0]), "=r"(r[1]), "=r"(r[2]), "=r"(r[3]) : "r"(addr));
}
__device__ __forceinline__ void mma_f16(float* d, const uint32_t* a,
                                        uint32_t b0, uint32_t b1){
    asm volatile("mma.sync.aligned.m16n8k16.row.col.f32.f16.f16.f32 "
        "{%0,%1,%2,%3}, {%4,%5,%6,%7}, {%8,%9}, {%0,%1,%2,%3};"
        : "+f"(d[0]), "+f"(d[1]), "+f"(d[2]), "+f"(d[3])
        : "r"(a[0]), "r"(a[1]), "r"(a[2]), "r"(a[3]), "r"(b0), "r"(b1));
}
__device__ __forceinline__ uint32_t pack_half2(float lo, float hi){
    uint32_t r;
    asm("cvt.rn.f16x2.f32 %0, %1, %2;" : "=r"(r) : "f"(hi), "f"(lo));
    return r;
}

// ===================== reductions ===========================================
__device__ __forceinline__ float blockReduceMax(float v){
    __shared__ float sh[8];
    int lid = threadIdx.x & 31, wid = threadIdx.x >> 5;
    #pragma unroll
    for (int o = 16; o > 0; o >>= 1) v = fmaxf(v, __shfl_xor_sync(0xffffffffu, v, o));
    if (lid == 0) sh[wid] = v;
    __syncthreads();
    v = sh[lid & 7];
    #pragma unroll
    for (int o = 4; o > 0; o >>= 1) v = fmaxf(v, __shfl_xor_sync(0xffffffffu, v, o));
    __syncthreads();
    return v;
}
__device__ __forceinline__ float blockReduceSum(float v){
    __shared__ float sh[8];
    int lid = threadIdx.x & 31, wid = threadIdx.x >> 5;
    #pragma unroll
    for (int o = 16; o > 0; o >>= 1) v += __shfl_xor_sync(0xffffffffu, v, o);
    if (lid == 0) sh[wid] = v;
    __syncthreads();
    v = sh[lid & 7];
    #pragma unroll
    for (int o = 4; o > 0; o >>= 1) v += __shfl_xor_sync(0xffffffffu, v, o);
    __syncthreads();
    return v;
}

// ===================== small kernels ========================================
__global__ void embed_k(const int* __restrict__ x,
                        const float* __restrict__ wte,
                        const float* __restrict__ wpe){
    int i = blockIdx.x * blockDim.x + threadIdx.x;
    if (i >= Mdim * Cdim) return;
    int c  = i % Cdim;
    int bt = i / Cdim;
    int t  = bt % Tdim;
    g_h[i] = wte[(size_t)x[bt] * Cdim + c] + wpe[(size_t)t * Cdim + c];
}

__global__ void cvt_h_k(const float* __restrict__ in, __half* __restrict__ o, long n){
    long stride = (long)gridDim.x * blockDim.x * 4;
    for (long i = ((long)blockIdx.x * blockDim.x + threadIdx.x) * 4; i < n; i += stride){
        float4 v = *(const float4*)(in + i);
        uint2 w;
        w.x = pack_half2(v.x, v.y);
        w.y = pack_half2(v.z, v.w);
        *(uint2*)(o + i) = w;
    }
}

__global__ void ln_k(const float* __restrict__ in,
                     const float* __restrict__ w,
                     const float* __restrict__ b,
                     __half* __restrict__ ohi,
                     __half* __restrict__ olo){
    int row = blockIdx.x, tid = threadIdx.x;
    const float* xp = in + (size_t)row * Cdim;
    float v[3], s = 0.f, ss = 0.f;
    #pragma unroll
    for (int i = 0; i < 3; i++){
        v[i] = xp[tid + i * 256];
        s += v[i]; ss += v[i] * v[i];
    }
    s  = blockReduceSum(s);
    ss = blockReduceSum(ss);
    float mean = s * (1.f / Cdim);
    float var  = ss * (1.f / Cdim) - mean * mean;
    float rstd = rsqrtf(var + 1e-5f);
    #pragma unroll
    for (int i = 0; i < 3; i++){
        int c = tid + i * 256;
        float y = (v[i] - mean) * rstd * w[c] + b[c];
        __half h = __float2half_rn(y);
        ohi[(size_t)row * Cdim + c] = h;
        olo[(size_t)row * Cdim + c] = __float2half_rn(y - __half2float(h));
    }
}

// ===================== fp16 2-term split GEMM (mma.sync) ====================
// C[M,N] = (Ahi+Alo)[M,K] @ B[N,K]^T.  A hi/lo fp16, B single fp16.
// N must be a multiple of 128. Split-K via gridDim.z (mode 2 only).
// modes: 1: relu(acc+bias)->hi/lo | 2: out_f atomicAdd(acc[+bias if z==0]) | 4: (acc+bias)->hi/lo
#define MAT_B   10240            /* 128 rows * 80 bytes */
#define STG_B   (3*MAT_B)
#define GT_SMEM (2*STG_B)        /* 61440 bytes */

__global__ __launch_bounds__(256, 2) void gemm_tc_k(
        const __half* __restrict__ Ahi, const __half* __restrict__ Alo,
        const __half* __restrict__ Bm,
        const float* __restrict__ bias,
        float* __restrict__ out_f,
        __half* __restrict__ out_hi, __half* __restrict__ out_lo,
        int N, int K, int mode){
    extern __shared__ char smem[];
    uint32_t sbase = smem_to_u32(smem);
    int tid = threadIdx.x, wid = tid >> 5, lane = tid & 31;
    int warpRow = wid >> 2, warpCol = wid & 3;

    long row0 = (long)blockIdx.x * 128;
    long n0   = (long)blockIdx.y * 128;
    int kspan = K / (int)gridDim.z;
    long kbase = (long)blockIdx.z * kspan;
    int nIter = kspan >> 5;

    float acc[4][4][4];
    #pragma unroll
    for (int i = 0; i < 4; i++)
        #pragma unroll
        for (int j = 0; j < 4; j++)
            #pragma unroll
            for (int q = 0; q < 4; q++) acc[i][j][q] = 0.f;

    auto issue = [&](int it){
        if (it >= nIter) return;
        long k0 = kbase + ((long)it << 5);
        uint32_t stg = sbase + (uint32_t)(it & 1) * STG_B;
        #pragma unroll
        for (int j = 0; j < 6; j++){
            int c   = tid + j * 256;          // 0..1535
            int mat = c >> 9;                  // 0:Ahi 1:Alo 2:B
            int id  = c & 511;
            int row = id >> 2;
            int c8  = (id & 3) << 3;
            const __half* src;
            if (mat < 2){
                src = (mat == 0 ? Ahi : Alo) + (row0 + row) * (long)K + k0 + c8;
            } else {
                src = Bm + (n0 + row) * (long)K + k0 + c8;
            }
            uint32_t dst = stg + (uint32_t)(mat * MAT_B + row * 80 + c8 * 2);
            cp_async16(dst, src);
        }
        CP_COMMIT();
    };

    issue(0);
    for (int it = 0; it < nIter; it++){
        CP_WAIT0();
        __syncthreads();        // data(it) visible + all warps done with compute(it-1)
        issue(it + 1);          // safely overwrites buffer of it-1

        uint32_t stg = sbase + (uint32_t)(it & 1) * STG_B;
        uint32_t aHi = stg;
        uint32_t aLo = stg + MAT_B;
        uint32_t bS  = stg + 2*MAT_B;
        uint32_t rsel = (uint32_t)(lane & 15) * 80 + (uint32_t)(lane >> 4) * 16;

        #pragma unroll
        for (int ks = 0; ks < 32; ks += 16){
            uint32_t bf[2][4];
            #pragma unroll
            for (int nj = 0; nj < 2; nj++){
                uint32_t off = (uint32_t)((warpCol*32 + nj*16) * 80 + ks*2) + rsel;
                ldsm_x4(bf[nj], bS + off);
            }
            #pragma unroll
            for (int mi = 0; mi < 4; mi++){
                uint32_t ah[4], al[4];
                uint32_t off = (uint32_t)((warpRow*64 + mi*16) * 80 + ks*2) + rsel;
                ldsm_x4(ah, aHi + off);
                ldsm_x4(al, aLo + off);
                #pragma unroll
                for (int ni = 0; ni < 4; ni++){
                    int nj = ni >> 1, w = ni & 1;
                    mma_f16(acc[mi][ni], ah, bf[nj][w], bf[nj][w+2]);
                    mma_f16(acc[mi][ni], al, bf[nj][w], bf[nj][w+2]);
                }
            }
        }
    }
    __syncthreads();

    bool addBias = (blockIdx.z == 0);
    #pragma unroll
    for (int mi = 0; mi < 4; mi++){
        long r0 = row0 + warpRow*64 + mi*16 + (lane >> 2);
        #pragma unroll
        for (int ni = 0; ni < 4; ni++){
            long c0 = n0 + warpCol*32 + ni*8 + (lane & 3)*2;
            float b0 = addBias ? bias[c0]     : 0.f;
            float b1 = addBias ? bias[c0 + 1] : 0.f;
            #pragma unroll
            for (int half = 0; half < 2; half++){
                long r  = r0 + half*8;
                long oi = r * (long)N + c0;
                float v0 = acc[mi][ni][half*2]     + b0;
                float v1 = acc[mi][ni][half*2 + 1] + b1;
                if (mode == 2){
                    atomicAdd(out_f + oi,     v0);
                    atomicAdd(out_f + oi + 1, v1);
                } else {
                    if (mode == 1){
                        v0 = fmaxf(v0, 0.f);
                        v1 = fmaxf(v1, 0.f);
                    }
                    float h0 = __half2float(__float2half_rn(v0));
                    float h1 = __half2float(__float2half_rn(v1));
                    *(uint32_t*)(out_hi + oi) = pack_half2(v0, v1);
                    *(uint32_t*)(out_lo + oi) = pack_half2(v0 - h0, v1 - h1);
                }
            }
        }
    }
}

// ===================== fp16 single-term GEMM (lm_head) ======================
#define FH_MAT  10240
#define FH_STG  (2*FH_MAT)
#define FH_SMEM (2*FH_STG)       /* 40960 */

__global__ __launch_bounds__(256, 2) void gemm_f16_k(
        const __half* __restrict__ A, const __half* __restrict__ Bm,
        float* __restrict__ out_f, int N, int K){
    extern __shared__ char smem[];
    uint32_t sbase = smem_to_u32(smem);
    int tid = threadIdx.x, wid = tid >> 5, lane = tid & 31;
    int warpRow = wid >> 2, warpCol = wid & 3;

    long row0 = (long)blockIdx.x * 128;
    long n0   = (long)blockIdx.y * 128;
    int nIter = K >> 5;

    float acc[4][4][4];
    #pragma unroll
    for (int i = 0; i < 4; i++)
        #pragma unroll
        for (int j = 0; j < 4; j++)
            #pragma unroll
            for (int q = 0; q < 4; q++) acc[i][j][q] = 0.f;

    auto issue = [&](int it){
        if (it >= nIter) return;
        int k0 = it << 5;
        uint32_t stg = sbase + (uint32_t)(it & 1) * FH_STG;
        #pragma unroll
        for (int j = 0; j < 4; j++){
            int c   = tid + j * 256;
            int mat = c >> 9;
            int id  = c & 511;
            int row = id >> 2;
            int c8  = (id & 3) << 3;
            const __half* src;
            if (mat == 0){
                src = A + (row0 + row) * (long)K + k0 + c8;
            } else {
                long br = n0 + row; if (br >= N) br = 0;
                src = Bm + br * (long)K + k0 + c8;
            }
            uint32_t dst = stg + (uint32_t)(mat * FH_MAT + row * 80 + c8 * 2);
            cp_async16(dst, src);
        }
        CP_COMMIT();
    };

    issue(0);
    for (int it = 0; it < nIter; it++){
        CP_WAIT0();
        __syncthreads();
        issue(it + 1);

        uint32_t stg = sbase + (uint32_t)(it & 1) * FH_STG;
        uint32_t aS = stg;
        uint32_t bS = stg + FH_MAT;
        uint32_t rsel = (uint32_t)(lane & 15) * 80 + (uint32_t)(lane >> 4) * 16;

        #pragma unroll
        for (int ks = 0; ks < 32; ks += 16){
            uint32_t bf[2][4];
            #pragma unroll
            for (int nj = 0; nj < 2; nj++){
                uint32_t off = (uint32_t)((warpCol*32 + nj*16) * 80 + ks*2) + rsel;
                ldsm_x4(bf[nj], bS + off);
            }
            #pragma unroll
            for (int mi = 0; mi < 4; mi++){
                uint32_t af[4];
                uint32_t off = (uint32_t)((warpRow*64 + mi*16) * 80 + ks*2) + rsel;
                ldsm_x4(af, aS + off);
                #pragma unroll
                for (int ni = 0; ni < 4; ni++){
                    int nj = ni >> 1, w = ni & 1;
                    mma_f16(acc[mi][ni], af, bf[nj][w], bf[nj][w+2]);
                }
            }
        }
    }

    // scalar stores: logits base pointer may be only 4B-aligned (out+1)
    #pragma unroll
    for (int mi = 0; mi < 4; mi++){
        long r0 = row0 + warpRow*64 + mi*16 + (lane >> 2);
        #pragma unroll
        for (int ni = 0; ni < 4; ni++){
            long c0 = n0 + warpCol*32 + ni*8 + (lane & 3)*2;
            #pragma unroll
            for (int half = 0; half < 2; half++){
                long r = r0 + half*8;
                #pragma unroll
                for (int e = 0; e < 2; e++){
                    long n = c0 + e;
                    if (n < N)
                        out_f[r * (long)N + n] = acc[mi][ni][half*2 + e];
                }
            }
        }
    }
}

// ===================== flash attention (fp16 mma, hi/lo split) ==============
#define FA_QB    (128*144)
#define FA_KVMAT (64*144)
#define FA_STGB  (4*FA_KVMAT)
#define FA_SMEM  (2*FA_QB + 2*FA_STGB)   /* 110592 */

__global__ __launch_bounds__(256, 2) void flash_k(
        const __half* __restrict__ qkvh,
        const __half* __restrict__ qkvl){
    extern __shared__ char smem[];
    uint32_t sb = smem_to_u32(smem);
    uint32_t Qh = sb, Ql = sb + FA_QB;
    uint32_t kvb = sb + 2*FA_QB;

    int tid = threadIdx.x, wid = tid >> 5, lane = tid & 31;
    int g = lane >> 2, tq = lane & 3;
    int qb = (int)gridDim.x - 1 - (int)blockIdx.x;
    int bh = blockIdx.y; int bq = bh / Hdim, head = bh % Hdim;
    int q0 = qb * 128;
    long rowbase = (long)bq * Tdim;

    #pragma unroll
    for (int j = 0; j < 8; j++){
        int id = tid + j*256;
        int mat = id >> 10, rem = id & 1023;
        int row = rem >> 3, c8 = (rem & 7) << 3;
        const __half* src = (mat ? qkvl : qkvh)
            + (rowbase + q0 + row)*(long)C3 + head*Ddim + c8;
        cp_async16((mat ? Ql : Qh) + (uint32_t)(row*144 + c8*2), src);
    }

    int nkv = 2*qb + 2;
    auto issue = [&](int j){
        if (j >= nkv) return;
        int s0 = j * 64;
        uint32_t stg = kvb + (uint32_t)(j & 1) * FA_STGB;
        #pragma unroll
        for (int jj = 0; jj < 8; jj++){
            int id = tid + jj*256;
            int mat = id >> 9, rem = id & 511;
            int row = rem >> 3, c8 = (rem & 7) << 3;
            const __half* base = (mat & 1) ? qkvl : qkvh;
            int coff = (mat < 2) ? Cdim : 2*Cdim;
            const __half* src = base
                + (rowbase + s0 + row)*(long)C3 + coff + head*Ddim + c8;
            cp_async16(stg + (uint32_t)(mat*FA_KVMAT + row*144 + c8*2), src);
        }
        CP_COMMIT();
    };

    float mrow[2] = {-1e30f, -1e30f};
    float lrow[2] = {0.f, 0.f};
    float oacc[8][4];
    #pragma unroll
    for (int i = 0; i < 8; i++)
        #pragma unroll
        for (int e = 0; e < 4; e++) oacc[i][e] = 0.f;

    int t0w = q0 + wid*16;
    uint32_t rsel16 = (uint32_t)(lane & 15)*144 + (uint32_t)(lane >> 4)*16;
    int vtsel = lane >> 3, vrt = lane & 7;
    uint32_t vrow_off = ((vtsel >> 1) ? 8u : 0u) + (uint32_t)vrt;
    uint32_t vcol_off = (vtsel & 1) ? 16u : 0u;

    issue(0);
    for (int j = 0; j < nkv; j++){
        CP_WAIT0();
        __syncthreads();        // data(j) visible + all warps done with compute(j-1)
        issue(j + 1);

        int s0 = j * 64;
        if (s0 <= t0w + 15){
            uint32_t stg = kvb + (uint32_t)(j & 1) * FA_STGB;
            uint32_t Kh = stg, Kl = stg + FA_KVMAT;
            uint32_t Vh = stg + 2*FA_KVMAT, Vl = stg + 3*FA_KVMAT;

            float S[8][4];
            #pragma unroll
            for (int i = 0; i < 8; i++)
                #pragma unroll
                for (int e = 0; e < 4; e++) S[i][e] = 0.f;

            #pragma unroll
            for (int dc = 0; dc < 4; dc++){
                uint32_t aoff = (uint32_t)(wid*16)*144 + (uint32_t)dc*32 + rsel16;
                uint32_t ah[4], al[4];
                ldsm_x4(ah, Qh + aoff);
                ldsm_x4(al, Ql + aoff);
                #pragma unroll
                for (int ng = 0; ng < 4; ng++){
                    uint32_t boff = (uint32_t)(ng*16)*144 + (uint32_t)dc*32 + rsel16;
                    uint32_t kh[4], kl[4];
                    ldsm_x4(kh, Kh + boff);
                    ldsm_x4(kl, Kl + boff);
                    #pragma unroll
                    for (int w = 0; w < 2; w++){
                        mma_f16(S[ng*2+w], ah, kh[w], kh[w+2]);
                        mma_f16(S[ng*2+w], ah, kl[w], kl[w+2]);
                        mma_f16(S[ng*2+w], al, kh[w], kh[w+2]);
                    }
                }
            }

            bool needMask = (s0 + 63 > t0w);
            #pragma unroll
            for (int ns = 0; ns < 8; ns++)
                #pragma unroll
                for (int e = 0; e < 4; e++){
                    float v = S[ns][e] * 0.125f;
                    if (needMask){
                        int t = t0w + g + (e >> 1)*8;
                        int s = s0 + ns*8 + tq*2 + (e & 1);
                        if (s > t) v = -1e30f;
                    }
                    S[ns][e] = v;
                }

            #pragma unroll
            for (int r = 0; r < 2; r++){
                float mx = -1e30f;
                #pragma unroll
                for (int ns = 0; ns < 8; ns++)
                    mx = fmaxf(mx, fmaxf(S[ns][r*2], S[ns][r*2+1]));
                mx = fmaxf(mx, __shfl_xor_sync(0xffffffffu, mx, 1));
                mx = fmaxf(mx, __shfl_xor_sync(0xffffffffu, mx, 2));
                float mnew = fmaxf(mrow[r], mx);
                float corr = __expf(mrow[r] - mnew);
                mrow[r] = mnew;
                float lsum = 0.f;
                #pragma unroll
                for (int ns = 0; ns < 8; ns++){
                    float p0 = __expf(S[ns][r*2]   - mnew);
                    float p1 = __expf(S[ns][r*2+1] - mnew);
                    S[ns][r*2] = p0; S[ns][r*2+1] = p1;
                    lsum += p0 + p1;
                }
                lsum += __shfl_xor_sync(0xffffffffu, lsum, 1);
                lsum += __shfl_xor_sync(0xffffffffu, lsum, 2);
                lrow[r] = lrow[r]*corr + lsum;
                #pragma unroll
                for (int dt = 0; dt < 8; dt++){
                    oacc[dt][r*2]   *= corr;
                    oacc[dt][r*2+1] *= corr;
                }
            }

            #pragma unroll
            for (int sc = 0; sc < 4; sc++){
                uint32_t ph[4], pl[4];
                #pragma unroll
                for (int half = 0; half < 2; half++){
                    int ns = sc*2 + half;
                    float v0 = S[ns][0], v1 = S[ns][1], v2 = S[ns][2], v3 = S[ns][3];
                    float h0 = __half2float(__float2half_rn(v0));
                    float h1 = __half2float(__float2half_rn(v1));
                    float h2 = __half2float(__float2half_rn(v2));
                    float h3 = __half2float(__float2half_rn(v3));
                    ph[half*2+0] = pack_half2(v0, v1);
                    ph[half*2+1] = pack_half2(v2, v3);
                    pl[half*2+0] = pack_half2(v0 - h0, v1 - h1);
                    pl[half*2+1] = pack_half2(v2 - h2, v3 - h3);
                }
                uint32_t vbase = (uint32_t)((sc*16 + vrow_off)*144) + vcol_off;
                #pragma unroll
                for (int dg = 0; dg < 4; dg++){
                    uint32_t vh_[4], vl_[4];
                    ldsm_x4_t(vh_, Vh + vbase + (uint32_t)dg*32);
                    ldsm_x4_t(vl_, Vl + vbase + (uint32_t)dg*32);
                    #pragma unroll
                    for (int w = 0; w < 2; w++){
                        int dt = dg*2 + w;
                        mma_f16(oacc[dt], ph, vh_[w], vh_[w+2]);
                        mma_f16(oacc[dt], ph, vl_[w], vl_[w+2]);
                        mma_f16(oacc[dt], pl, vh_[w], vh_[w+2]);
                    }
                }
            }
        }
    }

    #pragma unroll
    for (int r = 0; r < 2; r++){
        float inv = 1.f / lrow[r];
        long t = (long)t0w + g + r*8;
        float* hp = g_h + (rowbase + t)*(long)Cdim + head*Ddim;
        #pragma unroll
        for (int dt = 0; dt < 8; dt++){
            float2* p = (float2*)(hp + dt*8 + tq*2);
            float2 v = *p;
            v.x += oacc[dt][r*2]   * inv;
            v.y += oacc[dt][r*2+1] * inv;
            *p = v;
        }
    }
}

// ===================== cross-entropy (single-pass online) ===================
__global__ void loss_row_k(const float* __restrict__ logits,
                           const int* __restrict__ target){
    int row = blockIdx.x, tid = threadIdx.x;
    const float* p = logits + (size_t)row * Vdim;
    float m = -1e30f, s = 0.f;
    for (int i = tid; i < Vdim; i += 256){
        float x = p[i];
        if (x > m){
            s = s * __expf(m - x) + 1.f;
            m = x;
        } else {
            s += __expf(x - m);
        }
    }
    float mg = blockReduceMax(m);
    s *= __expf(m - mg);
    float tot = blockReduceSum(s);
    if (tid == 0){
        float lse = logf(tot) + mg;
        g_rowloss[row] = lse - p[target[row]];
    }
}
__global__ void loss_reduce_k(float* out){
    float s = 0.f;
    for (int i = threadIdx.x; i < Mdim; i += 256) s += g_rowloss[i];
    s = blockReduceSum(s);
    if (threadIdx.x == 0) out[0] = s / (float)Mdim;
}

// ===================== launch ===============================================
extern "C" void kernel_launch(void* const* d_in, const int* in_sizes, int n_in,
                              void* d_out, int out_size){
    const int*   x      = (const int*)  d_in[0];
    const int*   target = (const int*)  d_in[1];
    const float* wte    = (const float*)d_in[2];
    const float* wpe    = (const float*)d_in[3];
    const float* ln1_w  = (const float*)d_in[4];
    const float* ln1_b  = (const float*)d_in[5];
    const float* attn_w = (const float*)d_in[6];
    const float* attn_b = (const float*)d_in[7];
    const float* ln2_w  = (const float*)d_in[8];
    const float* ln2_b  = (const float*)d_in[9];
    const float* ff1_w  = (const float*)d_in[10];
    const float* ff1_b  = (const float*)d_in[11];
    const float* ff2_w  = (const float*)d_in[12];
    const float* ff2_b  = (const float*)d_in[13];
    const float* lm_w   = (const float*)d_in[14];

    float* out = (float*)d_out;
    bool has_loss = ((long long)out_size == (long long)Mdim * Vdim + 1);
    float* logits = has_loss ? out + 1 : out;

    cudaFuncSetAttribute(gemm_tc_k,  cudaFuncAttributeMaxDynamicSharedMemorySize, GT_SMEM);
    cudaFuncSetAttribute(gemm_f16_k, cudaFuncAttributeMaxDynamicSharedMemorySize, FH_SMEM);
    cudaFuncSetAttribute(flash_k,    cudaFuncAttributeMaxDynamicSharedMemorySize, FA_SMEM);

    float* ph;
    cudaGetSymbolAddress((void**)&ph, g_h);
    __half *wqk,*wf1,*wf2,*wlm;
    __half *xnh,*xnl,*fhh,*fhl,*qvh,*qvl,*ah_h;
    cudaGetSymbolAddress((void**)&wqk, g_wqkv_h);
    cudaGetSymbolAddress((void**)&wf1, g_wff1_h);
    cudaGetSymbolAddress((void**)&wf2, g_wff2_h);
    cudaGetSymbolAddress((void**)&wlm, g_wlm_h);
    cudaGetSymbolAddress((void**)&xnh, g_xn_hi);   cudaGetSymbolAddress((void**)&xnl, g_xn_lo);
    cudaGetSymbolAddress((void**)&fhh, g_ffh_hi);  cudaGetSymbolAddress((void**)&fhl, g_ffh_lo);
    cudaGetSymbolAddress((void**)&ah_h, g_ah_h);
    cudaGetSymbolAddress((void**)&qvh, g_qkv_hi);  cudaGetSymbolAddress((void**)&qvl, g_qkv_lo);

    cvt_h_k<<<2048, 256>>>(attn_w, wqk, (long)Ldim*C3*Cdim);
    cvt_h_k<<<2048, 256>>>(ff1_w,  wf1, (long)Ldim*Fdim*Cdim);
    cvt_h_k<<<2048, 256>>>(ff2_w,  wf2, (long)Ldim*Cdim*Fdim);
    cvt_h_k<<<4096, 256>>>(lm_w,   wlm, (long)Vdim*Cdim);

    embed_k<<<(Mdim*Cdim + 255)/256, 256>>>(x, wte, wpe);

    for (int l = 0; l < Ldim; l++){
        ln_k<<<Mdim, 256>>>(ph, ln1_w + (size_t)l*Cdim, ln1_b + (size_t)l*Cdim, xnh, xnl);

        gemm_tc_k<<<dim3(Mdim/128, C3/128, 1), 256, GT_SMEM>>>(
            xnh, xnl, wqk + (size_t)l*C3*Cdim,
            attn_b + (size_t)l*C3, nullptr, qvh, qvl, C3, Cdim, 4);

        flash_k<<<dim3(Tdim/128, Bdim*Hdim), 256, FA_SMEM>>>(qvh, qvl);

        ln_k<<<Mdim, 256>>>(ph, ln2_w + (size_t)l*Cdim, ln2_b + (size_t)l*Cdim, xnh, xnl);

        gemm_tc_k<<<dim3(Mdim/128, Fdim/128, 1), 256, GT_SMEM>>>(
            xnh, xnl, wf1 + (size_t)l*Fdim*Cdim,
            ff1_b + (size_t)l*Fdim, nullptr, fhh, fhl, Fdim, Cdim, 1);

        // split-K x2: 384 CTAs (fills the resident slots)
        gemm_tc_k<<<dim3(Mdim/128, Cdim/128, 2), 256, GT_SMEM>>>(
            fhh, fhl, wf2 + (size_t)l*Cdim*Fdim,
            ff2_b + (size_t)l*Cdim, ph, nullptr, nullptr, Cdim, Fdim, 2);
    }

    cvt_h_k<<<2048, 256>>>(ph, ah_h, (long)Mdim*Cdim);

    gemm_f16_k<<<dim3(Mdim/128, (Vdim + 127)/128), 256, FH_SMEM>>>(
        ah_h, wlm, logits, Vdim, Cdim);

    loss_row_k<<<Mdim, 256>>>(logits, target);
    if (has_loss)
        loss_reduce_k<<<1, 256>>>(out);
}